// round 3
// baseline (speedup 1.0000x reference)
#include <cuda_runtime.h>
#include <math.h>

// ---------------------------------------------------------------------------
// Shapes: B=4, C=256, H=W=128. Outputs (float32, concatenated):
//   prior_feature (4,100,256) at [0, 102400)
//   prior_anchor  (4,100,11)  at [102400, 106800)
//   topk_score    (4,100)     at [106800, 107200)
// ---------------------------------------------------------------------------

__device__ float g_feat[4ull * 256 * 128 * 128];   // conv1 output (relu(bn(conv)))
__device__ float g_hbuf[4ull * 256 * 128 * 128];   // conv2 output
__device__ float g_score[4 * 16384];               // sigmoid heatmap
__device__ int   g_tki[400];                       // topk indices
__device__ float g_tkv[400];                       // topk scores

// ---------------------------------------------------------------------------
// 3x3 conv (pad 1) + BN + ReLU.  Block: one (b, y) row x 128 output channels.
// grid = (2, 128, 4), 256 threads, 8x8 register tile per thread.
// ---------------------------------------------------------------------------
__global__ __launch_bounds__(256, 2)
void conv3x3_bn_relu(const float* __restrict__ in, const float* __restrict__ w,
                     const float* __restrict__ bg, const float* __restrict__ bb,
                     const float* __restrict__ bm, const float* __restrict__ bv,
                     float* __restrict__ out)
{
    const int nb = blockIdx.x;       // output-channel block: 0..1
    const int y  = blockIdx.y;       // row 0..127
    const int b  = blockIdx.z;       // batch 0..3
    const int n0 = nb * 128;

    __shared__ float Ash[3 * 4 * 132];   // [row r][chan cc][x+1], halo x in [-1,128]
    __shared__ float Bsh[36 * 128];      // [cc*9 + ky*3 + kx][n]

    const int tid = threadIdx.x;
    const int tx = tid & 15;             // x group
    const int ty = tid >> 4;             // n group

    float acc[8][8];
#pragma unroll
    for (int i = 0; i < 8; i++)
#pragma unroll
        for (int j = 0; j < 8; j++) acc[i][j] = 0.f;

    const float* inB = in + ((size_t)b << 22);    // b*256*16384

    // Precompute this thread's fixed A-staging coordinates (6 slots of 260
    // = 2 slots per row-r; 1560 total elements, 256 threads -> ceil 7 iters,
    // use simple strided loop with constant divisors).
    for (int c0 = 0; c0 < 256; c0 += 4) {
        __syncthreads();
        // Stage A: 3 input rows (y-1..y+1) x 4 channels x 130 x-values (pad)
        for (int i = tid; i < 3 * 4 * 130; i += 256) {
            int r   = i / 520;                 // 0..2
            int rem = i - r * 520;
            int c   = rem / 130;               // 0..3
            int xi  = rem - c * 130;           // stored index, x_in = xi-1
            int yy  = y + r - 1;
            int xin = xi - 1;
            float v = 0.f;
            if ((unsigned)yy < 128u && (unsigned)xin < 128u)
                v = inB[(((size_t)(c0 + c)) << 14) + (yy << 7) + xin];
            Ash[(r * 4 + c) * 132 + xi] = v;
        }
        // Stage B: weights for this c-chunk: w[n][c][ky][kx] (OIHW), j contiguous
        for (int i = tid; i < 4 * 9 * 128; i += 256) {
            int n = i / 36;
            int j = i - n * 36;                // j = c_local*9 + ky*3 + kx
            Bsh[j * 128 + n] = w[(size_t)(n0 + n) * 2304 + (size_t)c0 * 9 + j];
        }
        __syncthreads();

#pragma unroll
        for (int cc = 0; cc < 4; cc++) {
#pragma unroll
            for (int ky = 0; ky < 3; ky++) {
                const float* arow = &Ash[(ky * 4 + cc) * 132];
#pragma unroll
                for (int kx = 0; kx < 3; kx++) {
                    float a0[8], b0[8];
#pragma unroll
                    for (int i2 = 0; i2 < 4; i2++) {
                        a0[i2]     = arow[tx * 4 + i2 + kx];
                        a0[4 + i2] = arow[64 + tx * 4 + i2 + kx];
                    }
                    const float* brow = &Bsh[(cc * 9 + ky * 3 + kx) * 128];
#pragma unroll
                    for (int j2 = 0; j2 < 4; j2++) {
                        b0[j2]     = brow[ty * 4 + j2];
                        b0[4 + j2] = brow[64 + ty * 4 + j2];
                    }
#pragma unroll
                    for (int i2 = 0; i2 < 8; i2++)
#pragma unroll
                        for (int j2 = 0; j2 < 8; j2++)
                            acc[i2][j2] = fmaf(a0[i2], b0[j2], acc[i2][j2]);
                }
            }
        }
    }

    // Epilogue: BN + ReLU, write NCHW
#pragma unroll
    for (int j2 = 0; j2 < 8; j2++) {
        int n = n0 + ((j2 < 4) ? (ty * 4 + j2) : (64 + ty * 4 + j2 - 4));
        float scale = bg[n] * rsqrtf(bv[n] + 1e-5f);
        float shift = bb[n] - bm[n] * scale;
        float* op = out + (((size_t)b * 256 + n) << 14) + (y << 7);
#pragma unroll
        for (int i2 = 0; i2 < 8; i2++) {
            int x = (i2 < 4) ? (tx * 4 + i2) : (64 + tx * 4 + i2 - 4);
            op[x] = fmaxf(fmaf(acc[i2][j2], scale, shift), 0.f);
        }
    }
}

// ---------------------------------------------------------------------------
// 1x1 conv over 256 channels + sigmoid -> per-pixel score.
// ---------------------------------------------------------------------------
__global__ __launch_bounds__(128)
void heat_kernel(const float* __restrict__ w2, const float* __restrict__ b2)
{
    int pix = blockIdx.x * 128 + threadIdx.x;       // 0..65535
    int b = pix >> 14, p = pix & 16383;
    const float* hp = g_hbuf + ((size_t)b << 22) + p;
    float s = 0.f;
#pragma unroll 8
    for (int c = 0; c < 256; c++)
        s = fmaf(hp[(size_t)c << 14], __ldg(&w2[c]), s);
    s += b2[0];
    g_score[pix] = 1.f / (1.f + expf(-s));
}

// ---------------------------------------------------------------------------
// Top-100 per batch (descending score, ties -> smaller index first, matching
// jax.lax.top_k stability). One block per batch, keys in dynamic smem.
// ---------------------------------------------------------------------------
__global__ __launch_bounds__(1024)
void topk_kernel()
{
    extern __shared__ unsigned U[];            // 16384 keys + 32 RU + 32 RI
    unsigned* RU = U + 16384;
    int* RI = (int*)(U + 16384 + 32);
    const int b = blockIdx.x, tid = threadIdx.x;
    const int lane = tid & 31, wid = tid >> 5;

    for (int i = tid; i < 16384; i += 1024) {
        unsigned u = __float_as_uint(g_score[(b << 14) + i]);
        u = (u & 0x80000000u) ? ~u : (u | 0x80000000u);   // order-preserving map
        U[i] = u;
    }
    __syncthreads();

    for (int k = 0; k < 100; k++) {
        unsigned bu = 0; int bi = 0x7FFFFFFF;
        for (int i = tid; i < 16384; i += 1024) {
            unsigned u = U[i];
            if (u > bu || (u == bu && i < bi)) { bu = u; bi = i; }
        }
#pragma unroll
        for (int off = 16; off; off >>= 1) {
            unsigned u2 = __shfl_down_sync(0xFFFFFFFFu, bu, off);
            int i2 = __shfl_down_sync(0xFFFFFFFFu, bi, off);
            if (u2 > bu || (u2 == bu && i2 < bi)) { bu = u2; bi = i2; }
        }
        if (lane == 0) { RU[wid] = bu; RI[wid] = bi; }
        __syncthreads();
        if (wid == 0) {
            bu = RU[lane]; bi = RI[lane];
#pragma unroll
            for (int off = 16; off; off >>= 1) {
                unsigned u2 = __shfl_down_sync(0xFFFFFFFFu, bu, off);
                int i2 = __shfl_down_sync(0xFFFFFFFFu, bi, off);
                if (u2 > bu || (u2 == bu && i2 < bi)) { bu = u2; bi = i2; }
            }
            if (lane == 0) {
                g_tki[b * 100 + k] = bi;
                g_tkv[b * 100 + k] = g_score[(b << 14) + bi];
                U[bi] = 0;                               // remove winner
            }
        }
        __syncthreads();
    }
}

// ---------------------------------------------------------------------------
// Per-prior head: gather feature, MLP (fc->LN->relu->fc)*(1+score), small
// regression heads, anchor assembly. One block per (k, b), 256 threads.
// ---------------------------------------------------------------------------
__global__ __launch_bounds__(256)
void heads_kernel(const float* __restrict__ ta,
                  const float* __restrict__ w1, const float* __restrict__ b1,
                  const float* __restrict__ lng, const float* __restrict__ lnb,
                  const float* __restrict__ w2, const float* __restrict__ b2,
                  const float* __restrict__ zw, const float* __restrict__ zb,
                  const float* __restrict__ dw, const float* __restrict__ db,
                  const float* __restrict__ yw, const float* __restrict__ yb,
                  const float* __restrict__ vw, const float* __restrict__ vb,
                  float* __restrict__ out)
{
    const int k = blockIdx.x, b = blockIdx.y;
    const int tid = threadIdx.x;
    __shared__ float g[256], x1[256], red[18], hv[8];

    const int idx = g_tki[b * 100 + k];
    const float sc = g_tkv[b * 100 + k];
    g[tid] = g_feat[(((size_t)b * 256 + tid) << 14) + idx];
    __syncthreads();

    // x = g @ w1^T + b1
    const float4* wr = (const float4*)(w1 + (size_t)tid * 256);
    float s = 0.f;
#pragma unroll 8
    for (int c4 = 0; c4 < 64; c4++) {
        float4 wv = wr[c4];
        const float* gp = &g[c4 * 4];
        s += wv.x * gp[0] + wv.y * gp[1] + wv.z * gp[2] + wv.w * gp[3];
    }
    s += b1[tid];

    // LayerNorm over 256
    float ss = s, sq = s * s;
#pragma unroll
    for (int off = 16; off; off >>= 1) {
        ss += __shfl_down_sync(0xFFFFFFFFu, ss, off);
        sq += __shfl_down_sync(0xFFFFFFFFu, sq, off);
    }
    const int lane = tid & 31, wd = tid >> 5;
    if (lane == 0) { red[wd] = ss; red[8 + wd] = sq; }
    __syncthreads();
    if (tid == 0) {
        float S = 0.f, Q = 0.f;
        for (int i = 0; i < 8; i++) { S += red[i]; Q += red[8 + i]; }
        float mu = S * (1.f / 256.f);
        float var = Q * (1.f / 256.f) - mu * mu;
        red[16] = mu; red[17] = rsqrtf(var + 1e-5f);
    }
    __syncthreads();
    float mu = red[16], inv = red[17];
    x1[tid] = fmaxf((s - mu) * inv * lng[tid] + lnb[tid], 0.f);

    // small regression heads (threads 0..7), over gathered features g
    if (tid < 8) {
        const float* hw; float hb;
        if (tid == 0)      { hw = zw;                   hb = zb[0]; }
        else if (tid < 4)  { hw = dw + (tid - 1) * 256; hb = db[tid - 1]; }
        else if (tid < 6)  { hw = yw + (tid - 4) * 256; hb = yb[tid - 4]; }
        else               { hw = vw + (tid - 6) * 256; hb = vb[tid - 6]; }
        float hs = hb;
        for (int c = 0; c < 256; c++) hs = fmaf(hw[c], g[c], hs);
        hv[tid] = hs;
    }
    __syncthreads();

    // prior_feature = (x1 @ w2^T + b2) * (1 + score)
    const float4* w2r = (const float4*)(w2 + (size_t)tid * 256);
    float s2 = 0.f;
#pragma unroll 8
    for (int c4 = 0; c4 < 64; c4++) {
        float4 wv = w2r[c4];
        const float* xp = &x1[c4 * 4];
        s2 += wv.x * xp[0] + wv.y * xp[1] + wv.z * xp[2] + wv.w * xp[3];
    }
    s2 = (s2 + b2[tid]) * (1.f + sc);
    out[((size_t)(b * 100 + k)) * 256 + tid] = s2;

    // anchor assembly (11 values)
    if (tid < 11) {
        const float* pa = ta + ((size_t)b * 900 + k) * 11;
        int xs = idx & 127, ys = idx >> 7;
        float val;
        if (tid == 0)      val = (xs + 0.5f) * 0.8f - 51.2f;
        else if (tid == 1) val = (ys + 0.5f) * 0.8f - 51.2f;
        else if (tid == 2) val = pa[2] + 0.5f * hv[0];
        else if (tid < 6)  val = pa[tid] + 0.2f * fminf(fmaxf(hv[tid - 2], -1.f), 1.f);
        else if (tid < 8) {
            float y0 = tanhf(hv[4]), y1 = tanhf(hv[5]);
            float nr = fmaxf(sqrtf(y0 * y0 + y1 * y1), 1e-6f);
            val = 0.7f * pa[tid] + 0.3f * ((tid == 6 ? y0 : y1) / nr);
        }
        else if (tid < 10) val = pa[tid] + 0.2f * fminf(fmaxf(hv[tid - 2], -2.f), 2.f);
        else               val = pa[10];
        out[102400 + (b * 100 + k) * 11 + tid] = val;
    }
    if (tid == 0) out[106800 + b * 100 + k] = sc;
}

// ---------------------------------------------------------------------------
extern "C" void kernel_launch(void* const* d_in, const int* in_sizes, int n_in,
                              void* d_out, int out_size)
{
    const float* bev  = (const float*)d_in[0];
    const float* ta   = (const float*)d_in[1];
    const float* sw   = (const float*)d_in[2];
    const float* bn1g = (const float*)d_in[3];
    const float* bn1b = (const float*)d_in[4];
    const float* bn1m = (const float*)d_in[5];
    const float* bn1v = (const float*)d_in[6];
    const float* ow1  = (const float*)d_in[7];
    const float* bn2g = (const float*)d_in[8];
    const float* bn2b = (const float*)d_in[9];
    const float* bn2m = (const float*)d_in[10];
    const float* bn2v = (const float*)d_in[11];
    const float* ow2  = (const float*)d_in[12];
    const float* ob2  = (const float*)d_in[13];
    const float* fpw1 = (const float*)d_in[14];
    const float* fpb1 = (const float*)d_in[15];
    const float* lng  = (const float*)d_in[16];
    const float* lnb  = (const float*)d_in[17];
    const float* fpw2 = (const float*)d_in[18];
    const float* fpb2 = (const float*)d_in[19];
    const float* zw   = (const float*)d_in[20];
    const float* zb   = (const float*)d_in[21];
    const float* dw   = (const float*)d_in[22];
    const float* db_  = (const float*)d_in[23];
    const float* yw   = (const float*)d_in[24];
    const float* yb   = (const float*)d_in[25];
    const float* vw   = (const float*)d_in[26];
    const float* vb   = (const float*)d_in[27];
    float* out = (float*)d_out;

    float* featp; float* hbufp;
    cudaGetSymbolAddress((void**)&featp, g_feat);
    cudaGetSymbolAddress((void**)&hbufp, g_hbuf);

    cudaFuncSetAttribute(topk_kernel,
                         cudaFuncAttributeMaxDynamicSharedMemorySize, 66 * 1024);

    dim3 cgrid(2, 128, 4);
    conv3x3_bn_relu<<<cgrid, 256>>>(bev, sw, bn1g, bn1b, bn1m, bn1v, featp);
    conv3x3_bn_relu<<<cgrid, 256>>>(featp, ow1, bn2g, bn2b, bn2m, bn2v, hbufp);
    heat_kernel<<<512, 128>>>(ow2, ob2);
    topk_kernel<<<4, 1024, (16384 + 64) * 4>>>();
    dim3 hgrid(100, 4);
    heads_kernel<<<hgrid, 256>>>(ta,
                                 fpw1, fpb1, lng, lnb, fpw2, fpb2,
                                 zw, zb, dw, db_, yw, yb, vw, vb, out);
}

// round 5
// speedup vs baseline: 1.3785x; 1.3785x over previous
#include <cuda_runtime.h>
#include <math.h>

typedef unsigned long long ull;

// ---------------------------------------------------------------------------
// Shapes: B=4, C=256, H=W=128. Outputs (float32, concatenated):
//   prior_feature (4,100,256) at [0, 102400)
//   prior_anchor  (4,100,11)  at [102400, 106800)
//   topk_score    (4,100)     at [106800, 107200)
// ---------------------------------------------------------------------------

__device__ float g_feat[4ull * 256 * 128 * 128];   // conv1 output (relu(bn(conv)))
__device__ float g_hbuf[4ull * 256 * 128 * 128];   // conv2 output
__device__ float g_score[4 * 16384];               // sigmoid heatmap
__device__ int   g_tki[400];                       // topk indices
__device__ float g_tkv[400];                       // topk scores

// Packed dual-FMA: d = a*b + d, lanewise fp32 (sm_103a FFMA2).
__device__ __forceinline__ void ffma2(ull& d, ull a, ull b) {
    asm("fma.rn.f32x2 %0, %1, %2, %0;" : "+l"(d) : "l"(a), "l"(b));
}
__device__ __forceinline__ ull dup2(float x) {
    ull p;
    asm("mov.b64 %0, {%1, %1};" : "=l"(p) : "f"(x));
    return p;
}
__device__ __forceinline__ void unpack2(ull p, float& lo, float& hi) {
    asm("mov.b64 {%0, %1}, %2;" : "=f"(lo), "=f"(hi) : "l"(p));
}

// ---------------------------------------------------------------------------
// 3x3 conv (pad 1) + BN + ReLU.  Block: one (b, y) row x 128 output channels.
// grid = (2, 128, 4), 256 threads. 8x8 output tile per thread held as
// 8x4 f32x2 accumulators (paired along n so B loads are aligned LDS.64).
// ---------------------------------------------------------------------------
__global__ __launch_bounds__(256, 2)
void conv3x3_bn_relu(const float* __restrict__ in, const float* __restrict__ w,
                     const float* __restrict__ bg, const float* __restrict__ bb,
                     const float* __restrict__ bm, const float* __restrict__ bv,
                     float* __restrict__ out)
{
    const int nb = blockIdx.x;       // output-channel block: 0..1
    const int y  = blockIdx.y;       // row 0..127
    const int b  = blockIdx.z;       // batch 0..3
    const int n0 = nb * 128;

    __shared__ float Ash[3 * 4 * 132];   // [row r][chan cc][x+1], halo x in [-1,128]
    __shared__ float Bsh[36 * 128];      // [cc*9 + ky*3 + kx][n]

    const int tid = threadIdx.x;
    const int tx = tid & 15;             // x group
    const int ty = tid >> 4;             // n group

    // acc2[i][p]: i -> x index (0..3: tx*4+i, 4..7: 64+tx*4+i-4)
    //             p -> n pair (0: ty*4+{0,1}, 1: ty*4+{2,3},
    //                          2: 64+ty*4+{0,1}, 3: 64+ty*4+{2,3})
    ull acc2[8][4];
#pragma unroll
    for (int i = 0; i < 8; i++)
#pragma unroll
        for (int j = 0; j < 4; j++) acc2[i][j] = 0ull;

    const float* inB = in + ((size_t)b << 22);    // b*256*16384

    for (int c0 = 0; c0 < 256; c0 += 4) {
        __syncthreads();
        // Stage A: 3 input rows (y-1..y+1) x 4 channels x 130 x-values (pad)
        for (int i = tid; i < 3 * 4 * 130; i += 256) {
            int r   = i / 520;                 // 0..2
            int rem = i - r * 520;
            int c   = rem / 130;               // 0..3
            int xi  = rem - c * 130;           // stored index, x_in = xi-1
            int yy  = y + r - 1;
            int xin = xi - 1;
            float v = 0.f;
            if ((unsigned)yy < 128u && (unsigned)xin < 128u)
                v = inB[(((size_t)(c0 + c)) << 14) + (yy << 7) + xin];
            Ash[(r * 4 + c) * 132 + xi] = v;
        }
        // Stage B: weights for this c-chunk: w[n][c][ky][kx] (OIHW), j contiguous
        for (int i = tid; i < 4 * 9 * 128; i += 256) {
            int n = i / 36;
            int j = i - n * 36;                // j = c_local*9 + ky*3 + kx
            Bsh[j * 128 + n] = w[(size_t)(n0 + n) * 2304 + (size_t)c0 * 9 + j];
        }
        __syncthreads();

#pragma unroll
        for (int cc = 0; cc < 4; cc++) {
#pragma unroll
            for (int ky = 0; ky < 3; ky++) {
                const float* arow = &Ash[(ky * 4 + cc) * 132];
                // Hoisted A window: 6 floats per half, covers all 3 kx taps.
                float aw[12];
                {
                    float4 w0 = *(const float4*)&arow[tx * 4];
                    float2 w0b = *(const float2*)&arow[tx * 4 + 4];
                    float4 w1 = *(const float4*)&arow[64 + tx * 4];
                    float2 w1b = *(const float2*)&arow[64 + tx * 4 + 4];
                    aw[0] = w0.x;  aw[1] = w0.y;  aw[2] = w0.z;
                    aw[3] = w0.w;  aw[4] = w0b.x; aw[5] = w0b.y;
                    aw[6] = w1.x;  aw[7] = w1.y;  aw[8] = w1.z;
                    aw[9] = w1.w;  aw[10] = w1b.x; aw[11] = w1b.y;
                }
#pragma unroll
                for (int kx = 0; kx < 3; kx++) {
                    const float* brow = &Bsh[(cc * 9 + ky * 3 + kx) * 128];
                    const ull* bplo = (const ull*)&brow[ty * 4];
                    const ull* bphi = (const ull*)&brow[64 + ty * 4];
                    ull b00 = bplo[0], b01 = bplo[1];
                    ull b10 = bphi[0], b11 = bphi[1];
                    ull ap[8];
#pragma unroll
                    for (int i2 = 0; i2 < 4; i2++) {
                        ap[i2]     = dup2(aw[i2 + kx]);
                        ap[4 + i2] = dup2(aw[6 + i2 + kx]);
                    }
#pragma unroll
                    for (int i2 = 0; i2 < 8; i2++) {
                        ffma2(acc2[i2][0], ap[i2], b00);
                        ffma2(acc2[i2][1], ap[i2], b01);
                        ffma2(acc2[i2][2], ap[i2], b10);
                        ffma2(acc2[i2][3], ap[i2], b11);
                    }
                }
            }
        }
    }

    // Epilogue: BN + ReLU, write NCHW
#pragma unroll
    for (int p = 0; p < 4; p++) {
        int nbase = n0 + ((p < 2) ? (ty * 4 + p * 2) : (64 + ty * 4 + (p - 2) * 2));
#pragma unroll
        for (int h = 0; h < 2; h++) {
            int n = nbase + h;
            float scale = bg[n] * rsqrtf(bv[n] + 1e-5f);
            float shift = bb[n] - bm[n] * scale;
            float* op = out + (((size_t)b * 256 + n) << 14) + (y << 7);
#pragma unroll
            for (int i2 = 0; i2 < 8; i2++) {
                int x = (i2 < 4) ? (tx * 4 + i2) : (64 + tx * 4 + i2 - 4);
                float lo, hi;
                unpack2(acc2[i2][p], lo, hi);
                float v = h ? hi : lo;
                op[x] = fmaxf(fmaf(v, scale, shift), 0.f);
            }
        }
    }
}

// ---------------------------------------------------------------------------
// 1x1 conv over 256 channels + sigmoid -> per-pixel score.
// ---------------------------------------------------------------------------
__global__ __launch_bounds__(128)
void heat_kernel(const float* __restrict__ w2, const float* __restrict__ b2)
{
    int pix = blockIdx.x * 128 + threadIdx.x;       // 0..65535
    int b = pix >> 14, p = pix & 16383;
    const float* hp = g_hbuf + ((size_t)b << 22) + p;
    float s = 0.f;
#pragma unroll 8
    for (int c = 0; c < 256; c++)
        s = fmaf(hp[(size_t)c << 14], __ldg(&w2[c]), s);
    s += b2[0];
    g_score[pix] = 1.f / (1.f + expf(-s));
}

// ---------------------------------------------------------------------------
// Top-100 per batch with segment-max caching. 512 threads; 512 segments of
// 32 elements. Per round: scan 512 segment maxima, localize winner in its
// 32-elem segment, zero it, repair that segment's max. Tie-breaking matches
// jax.lax.top_k (stable: smallest index among equal keys).
// ---------------------------------------------------------------------------
__global__ __launch_bounds__(512)
void topk_kernel()
{
    extern __shared__ unsigned U[];            // [16384] keys
    unsigned* S  = U + 16384;                  // [512] segment maxima
    unsigned* RU = S + 512;                    // [16] warp partial keys
    int*      RI = (int*)(RU + 16);            // [16] warp partial seg idx

    const int b = blockIdx.x, tid = threadIdx.x;
    const int lane = tid & 31, wid = tid >> 5;

    for (int i = tid; i < 16384; i += 512) {
        unsigned u = __float_as_uint(g_score[(b << 14) + i]);
        u = (u & 0x80000000u) ? ~u : (u | 0x80000000u);   // order-preserving map
        U[i] = u;                                         // scores>0 -> key>0
    }
    __syncthreads();

    {   // per-thread segment max (value only)
        unsigned m = 0;
        const int base = tid * 32;
#pragma unroll 8
        for (int j = 0; j < 32; j++) m = max(m, U[base + j]);
        S[tid] = m;
    }
    __syncthreads();

    for (int k = 0; k < 100; k++) {
        unsigned v = S[tid];
        int si = tid;
#pragma unroll
        for (int off = 16; off; off >>= 1) {
            unsigned v2 = __shfl_down_sync(0xFFFFFFFFu, v, off);
            int s2 = __shfl_down_sync(0xFFFFFFFFu, si, off);
            if (v2 > v || (v2 == v && s2 < si)) { v = v2; si = s2; }
        }
        if (lane == 0) { RU[wid] = v; RI[wid] = si; }
        __syncthreads();
        if (wid == 0) {
            unsigned vv = (lane < 16) ? RU[lane] : 0u;
            int ss = (lane < 16) ? RI[lane] : 0x7FFFFFFF;
#pragma unroll
            for (int off = 8; off; off >>= 1) {
                unsigned v2 = __shfl_down_sync(0xFFFFFFFFu, vv, off);
                int s2 = __shfl_down_sync(0xFFFFFFFFu, ss, off);
                if (v2 > vv || (v2 == vv && s2 < ss)) { vv = v2; ss = s2; }
            }
            vv = __shfl_sync(0xFFFFFFFFu, vv, 0);
            ss = __shfl_sync(0xFFFFFFFFu, ss, 0);
            // localize inside winning segment (smallest lane among equals)
            unsigned u = U[ss * 32 + lane];
            unsigned bal = __ballot_sync(0xFFFFFFFFu, u == vv);
            int li = __ffs(bal) - 1;
            if (lane == 0) {
                int gi = ss * 32 + li;
                g_tki[b * 100 + k] = gi;
                g_tkv[b * 100 + k] = g_score[(b << 14) + gi];
            }
            unsigned nu = (lane == li) ? 0u : u;
            U[ss * 32 + lane] = nu;
            unsigned m = nu;
#pragma unroll
            for (int off = 16; off; off >>= 1)
                m = max(m, __shfl_down_sync(0xFFFFFFFFu, m, off));
            if (lane == 0) S[ss] = m;
        }
        __syncthreads();
    }
}

// ---------------------------------------------------------------------------
// Per-prior head: gather feature, MLP (fc->LN->relu->fc)*(1+score), small
// regression heads, anchor assembly. One block per (k, b), 256 threads.
// ---------------------------------------------------------------------------
__global__ __launch_bounds__(256)
void heads_kernel(const float* __restrict__ ta,
                  const float* __restrict__ w1, const float* __restrict__ b1,
                  const float* __restrict__ lng, const float* __restrict__ lnb,
                  const float* __restrict__ w2, const float* __restrict__ b2,
                  const float* __restrict__ zw, const float* __restrict__ zb,
                  const float* __restrict__ dw, const float* __restrict__ db,
                  const float* __restrict__ yw, const float* __restrict__ yb,
                  const float* __restrict__ vw, const float* __restrict__ vb,
                  float* __restrict__ out)
{
    const int k = blockIdx.x, b = blockIdx.y;
    const int tid = threadIdx.x;
    __shared__ float g[256], x1[256], red[18], hv[8];

    const int idx = g_tki[b * 100 + k];
    const float sc = g_tkv[b * 100 + k];
    g[tid] = g_feat[(((size_t)b * 256 + tid) << 14) + idx];
    __syncthreads();

    // x = g @ w1^T + b1
    const float4* wr = (const float4*)(w1 + (size_t)tid * 256);
    float s = 0.f;
#pragma unroll 8
    for (int c4 = 0; c4 < 64; c4++) {
        float4 wv = wr[c4];
        const float* gp = &g[c4 * 4];
        s += wv.x * gp[0] + wv.y * gp[1] + wv.z * gp[2] + wv.w * gp[3];
    }
    s += b1[tid];

    // LayerNorm over 256
    float ss = s, sq = s * s;
#pragma unroll
    for (int off = 16; off; off >>= 1) {
        ss += __shfl_down_sync(0xFFFFFFFFu, ss, off);
        sq += __shfl_down_sync(0xFFFFFFFFu, sq, off);
    }
    const int lane = tid & 31, wd = tid >> 5;
    if (lane == 0) { red[wd] = ss; red[8 + wd] = sq; }
    __syncthreads();
    if (tid == 0) {
        float S = 0.f, Q = 0.f;
        for (int i = 0; i < 8; i++) { S += red[i]; Q += red[8 + i]; }
        float mu = S * (1.f / 256.f);
        float var = Q * (1.f / 256.f) - mu * mu;
        red[16] = mu; red[17] = rsqrtf(var + 1e-5f);
    }
    __syncthreads();
    float mu = red[16], inv = red[17];
    x1[tid] = fmaxf((s - mu) * inv * lng[tid] + lnb[tid], 0.f);

    // small regression heads (threads 0..7), over gathered features g
    if (tid < 8) {
        const float* hw; float hb;
        if (tid == 0)      { hw = zw;                   hb = zb[0]; }
        else if (tid < 4)  { hw = dw + (tid - 1) * 256; hb = db[tid - 1]; }
        else if (tid < 6)  { hw = yw + (tid - 4) * 256; hb = yb[tid - 4]; }
        else               { hw = vw + (tid - 6) * 256; hb = vb[tid - 6]; }
        float hs = hb;
        for (int c = 0; c < 256; c++) hs = fmaf(hw[c], g[c], hs);
        hv[tid] = hs;
    }
    __syncthreads();

    // prior_feature = (x1 @ w2^T + b2) * (1 + score)
    const float4* w2r = (const float4*)(w2 + (size_t)tid * 256);
    float s2 = 0.f;
#pragma unroll 8
    for (int c4 = 0; c4 < 64; c4++) {
        float4 wv = w2r[c4];
        const float* xp = &x1[c4 * 4];
        s2 += wv.x * xp[0] + wv.y * xp[1] + wv.z * xp[2] + wv.w * xp[3];
    }
    s2 = (s2 + b2[tid]) * (1.f + sc);
    out[((size_t)(b * 100 + k)) * 256 + tid] = s2;

    // anchor assembly (11 values)
    if (tid < 11) {
        const float* pa = ta + ((size_t)b * 900 + k) * 11;
        int xs = idx & 127, ys = idx >> 7;
        float val;
        if (tid == 0)      val = (xs + 0.5f) * 0.8f - 51.2f;
        else if (tid == 1) val = (ys + 0.5f) * 0.8f - 51.2f;
        else if (tid == 2) val = pa[2] + 0.5f * hv[0];
        else if (tid < 6)  val = pa[tid] + 0.2f * fminf(fmaxf(hv[tid - 2], -1.f), 1.f);
        else if (tid < 8) {
            float y0 = tanhf(hv[4]), y1 = tanhf(hv[5]);
            float nr = fmaxf(sqrtf(y0 * y0 + y1 * y1), 1e-6f);
            val = 0.7f * pa[tid] + 0.3f * ((tid == 6 ? y0 : y1) / nr);
        }
        else if (tid < 10) val = pa[tid] + 0.2f * fminf(fmaxf(hv[tid - 2], -2.f), 2.f);
        else               val = pa[10];
        out[102400 + (b * 100 + k) * 11 + tid] = val;
    }
    if (tid == 0) out[106800 + b * 100 + k] = sc;
}

// ---------------------------------------------------------------------------
extern "C" void kernel_launch(void* const* d_in, const int* in_sizes, int n_in,
                              void* d_out, int out_size)
{
    const float* bev  = (const float*)d_in[0];
    const float* ta   = (const float*)d_in[1];
    const float* sw   = (const float*)d_in[2];
    const float* bn1g = (const float*)d_in[3];
    const float* bn1b = (const float*)d_in[4];
    const float* bn1m = (const float*)d_in[5];
    const float* bn1v = (const float*)d_in[6];
    const float* ow1  = (const float*)d_in[7];
    const float* bn2g = (const float*)d_in[8];
    const float* bn2b = (const float*)d_in[9];
    const float* bn2m = (const float*)d_in[10];
    const float* bn2v = (const float*)d_in[11];
    const float* ow2  = (const float*)d_in[12];
    const float* ob2  = (const float*)d_in[13];
    const float* fpw1 = (const float*)d_in[14];
    const float* fpb1 = (const float*)d_in[15];
    const float* lng  = (const float*)d_in[16];
    const float* lnb  = (const float*)d_in[17];
    const float* fpw2 = (const float*)d_in[18];
    const float* fpb2 = (const float*)d_in[19];
    const float* zw   = (const float*)d_in[20];
    const float* zb   = (const float*)d_in[21];
    const float* dw   = (const float*)d_in[22];
    const float* db_  = (const float*)d_in[23];
    const float* yw   = (const float*)d_in[24];
    const float* yb   = (const float*)d_in[25];
    const float* vw   = (const float*)d_in[26];
    const float* vb   = (const float*)d_in[27];
    float* out = (float*)d_out;

    float* featp; float* hbufp;
    cudaGetSymbolAddress((void**)&featp, g_feat);
    cudaGetSymbolAddress((void**)&hbufp, g_hbuf);

    cudaFuncSetAttribute(topk_kernel,
                         cudaFuncAttributeMaxDynamicSharedMemorySize, 68 * 1024);

    dim3 cgrid(2, 128, 4);
    conv3x3_bn_relu<<<cgrid, 256>>>(bev, sw, bn1g, bn1b, bn1m, bn1v, featp);
    conv3x3_bn_relu<<<cgrid, 256>>>(featp, ow1, bn2g, bn2b, bn2m, bn2v, hbufp);
    heat_kernel<<<512, 128>>>(ow2, ob2);
    topk_kernel<<<4, 512, (16384 + 512 + 32) * 4>>>();
    dim3 hgrid(100, 4);
    heads_kernel<<<hgrid, 256>>>(ta,
                                 fpw1, fpb1, lng, lnb, fpw2, fpb2,
                                 zw, zb, dw, db_, yw, yb, vw, vb, out);
}